// round 8
// baseline (speedup 1.0000x reference)
#include <cuda_runtime.h>
#include <math.h>

// X is (65536, 512) fp32 row-major.
// NOTE: verbatim resubmission of the round-7 kernel — round-7 bench died with
// the recurring container-level infra error (rounds 1 and 3 failed the same
// way and the identical kernels passed on resubmission).
#define CDIM 512
#define BDIM 65536
#define CHUNK 16                 // rows per work unit
#define NCH  (BDIM / CHUNK)      // 4096 units
#define NBP  888                 // persistent blocks (148 SMs x 6)
#define NB2  74                  // stage-2a blocks: each reduces 12 partial rows

// Static device scratch (no allocations allowed).
__device__ __align__(16) float g_sumP[NBP][CDIM];
__device__ __align__(16) float g_maxP[NBP][CDIM];
__device__ __align__(16) float g_minP[NBP][CDIM];
__device__ __align__(16) float g_sum2[NB2][CDIM];
__device__ __align__(16) float g_max2[NB2][CDIM];
__device__ __align__(16) float g_min2[NB2][CDIM];
__device__ __align__(16) float g_mean[CDIM];
__device__ __align__(16) float g_c1[CDIM];
__device__ __align__(16) float g_c2[CDIM];
__device__ __align__(16) float g_wc[CDIM];
__device__ float g_sn1;

#define ACC4(v)                                                   \
    do {                                                          \
        s.x += (v).x; s.y += (v).y; s.z += (v).z; s.w += (v).w;   \
        mx.x = fmaxf(mx.x, (v).x); mx.y = fmaxf(mx.y, (v).y);     \
        mx.z = fmaxf(mx.z, (v).z); mx.w = fmaxf(mx.w, (v).w);     \
        mn.x = fminf(mn.x, (v).x); mn.y = fminf(mn.y, (v).y);     \
        mn.z = fminf(mn.z, (v).z); mn.w = fminf(mn.w, (v).w);     \
    } while (0)

// ---------------------------------------------------------------------------
// Pass 1 (persistent, single wave): 888 blocks x 256 threads. Block b owns a
// contiguous proportional slice of the 4096 16-row units; register
// accumulators carry across units and are written ONCE at block end ->
// partial footprint 888 rows (1.8 MiB x3). 256 threads = 128 float4
// column-groups x 2 row parities (8 rows each per unit). Loads issued in
// explicit batches of 4 before accumulation (MLP >= 4; proven in R6).
// Default cache policy on X (pass3 harvests the L2-resident tail).
// ---------------------------------------------------------------------------
__global__ void __launch_bounds__(256) k_pass1(const float* __restrict__ X) {
    const int tc = threadIdx.x & 127;   // column group 0..127
    const int tr = threadIdx.x >> 7;    // row parity 0..1
    const int b = blockIdx.x;
    const int u0 = (int)(((long long)b * NCH) / NBP);
    const int u1 = (int)(((long long)(b + 1) * NCH) / NBP);
    const float4* Xp = reinterpret_cast<const float4*>(X);
    const size_t rs = CDIM / 4;         // float4 row stride

    float4 s  = make_float4(0.f, 0.f, 0.f, 0.f);
    float4 mx = make_float4(-INFINITY, -INFINITY, -INFINITY, -INFINITY);
    float4 mn = make_float4( INFINITY,  INFINITY,  INFINITY,  INFINITY);

    for (int u = u0; u < u1; u++) {
        // parity tr owns rows {tr, tr+2, ..., tr+14} of this 16-row unit
        size_t base = ((size_t)u * CHUNK + tr) * rs + tc;
        float4 v0 = Xp[base + 0 * rs];
        float4 v1 = Xp[base + 2 * rs];
        float4 v2 = Xp[base + 4 * rs];
        float4 v3 = Xp[base + 6 * rs];
        ACC4(v0); ACC4(v1); ACC4(v2); ACC4(v3);
        float4 v4 = Xp[base +  8 * rs];
        float4 v5 = Xp[base + 10 * rs];
        float4 v6 = Xp[base + 12 * rs];
        float4 v7 = Xp[base + 14 * rs];
        ACC4(v4); ACC4(v5); ACC4(v6); ACC4(v7);
    }

    __shared__ float4 shS[128], shA[128], shI[128];
    if (tr == 1) { shS[tc] = s; shA[tc] = mx; shI[tc] = mn; }
    __syncthreads();
    if (tr == 0) {
        float4 s2 = shS[tc], a2 = shA[tc], i2 = shI[tc];
        s.x += s2.x; s.y += s2.y; s.z += s2.z; s.w += s2.w;
        mx.x = fmaxf(mx.x, a2.x); mx.y = fmaxf(mx.y, a2.y);
        mx.z = fmaxf(mx.z, a2.z); mx.w = fmaxf(mx.w, a2.w);
        mn.x = fminf(mn.x, i2.x); mn.y = fminf(mn.y, i2.y);
        mn.z = fminf(mn.z, i2.z); mn.w = fminf(mn.w, i2.w);
        __stcs(reinterpret_cast<float4*>(g_sumP[b]) + tc, s);
        __stcs(reinterpret_cast<float4*>(g_maxP[b]) + tc, mx);
        __stcs(reinterpret_cast<float4*>(g_minP[b]) + tc, mn);
    }
}

// ---------------------------------------------------------------------------
// Stage 2a: 74 blocks x 512 threads. Block b reduces whole partial rows
// [b*12, b*12+12): thread j owns column j -> fully coalesced 2 KiB row
// reads. Emits one row per block.
// ---------------------------------------------------------------------------
__global__ void k_stage2a() {
    const int j = threadIdx.x;    // column 0..511
    const int b = blockIdx.x;     // 0..73
    const int r0 = b * (NBP / NB2);   // 12 rows each

    float s = 0.f, mx = -INFINITY, mn = INFINITY;
#pragma unroll
    for (int r = 0; r < NBP / NB2; r++) {
        s += g_sumP[r0 + r][j];
        mx = fmaxf(mx, g_maxP[r0 + r][j]);
        mn = fminf(mn, g_minP[r0 + r][j]);
    }
    g_sum2[b][j] = s;
    g_max2[b][j] = mx;
    g_min2[b][j] = mn;
}

// ---------------------------------------------------------------------------
// Stage 2b: one block, 512 threads. Finishes the 74-row reduce per column,
// computes mean/u/dev, three global maxima -> SN1/SN2/SN3, and the fused
// per-column constants for pass3.
// ---------------------------------------------------------------------------
__device__ __forceinline__ float pow2_floor_log2(float v) {
    // replicates exp2(floor(log2(floor(v)))) including the v<1 -> 0 edge
    float f = floorf(v);
    if (f < 1.0f) return 0.0f;
    return ldexpf(1.0f, ilogbf(f));
}

__global__ void k_stage2b(const float* __restrict__ w,
                          const float* __restrict__ bia) {
    const int j = threadIdx.x;  // 0..511

    float s = 0.f, mx = -INFINITY, mn = INFINITY;
#pragma unroll
    for (int r = 0; r < NB2; r++) {
        s += g_sum2[r][j];
        mx = fmaxf(mx, g_max2[r][j]);
        mn = fminf(mn, g_min2[r][j]);
    }
    const float cb = (float)(1.0 / sqrt(2.0 * log((double)BDIM)));
    float mean = s * (1.0f / (float)BDIM);     // /2^16: exact scaling
    float uv   = cb * (mx - mn);
    float dev  = fmaxf(mx - mean, mean - mn);  // = max_i |x[i,j]-mean_j|

    float wv = w[j];
    float bv = bia[j];

    __shared__ float sh[CDIM];
    __shared__ float s_dmax, s_wmax, s_sn1, s_sn2, s_sn3;

    // dmax = max over cols of max(|q|_col, |u|_col)
    sh[j] = fmaxf(dev, fabsf(uv));
    __syncthreads();
    for (int off = 256; off > 0; off >>= 1) {
        if (j < off) sh[j] = fmaxf(sh[j], sh[j + off]);
        __syncthreads();
    }
    if (j == 0) s_dmax = (sh[0] == 0.f) ? 1.f : sh[0];
    __syncthreads();

    sh[j] = fabsf(wv);
    __syncthreads();
    for (int off = 256; off > 0; off >>= 1) {
        if (j < off) sh[j] = fmaxf(sh[j], sh[j + off]);
        __syncthreads();
    }
    if (j == 0) s_wmax = (sh[0] == 0.f) ? 1.f : sh[0];
    __syncthreads();

    sh[j] = fabsf(bv);
    __syncthreads();
    for (int off = 256; off > 0; off >>= 1) {
        if (j < off) sh[j] = fmaxf(sh[j], sh[j + off]);
        __syncthreads();
    }
    if (j == 0) {
        float bmax = (sh[0] == 0.f) ? 1.f : sh[0];
        s_sn1 = pow2_floor_log2(32.0f / s_dmax);
        s_sn2 = pow2_floor_log2(32.0f / s_wmax);
        s_sn3 = pow2_floor_log2(32.0f / bmax);
        g_sn1 = s_sn1;
    }
    __syncthreads();

    const float SN1 = s_sn1, SN2 = s_sn2, SN3 = s_sn3;

    int uu = (int)(uv * SN1);       // trunc toward zero == astype(int32)
    int ww = (int)(wv * SN2);
    int bq = (int)(bv * SN3);

    int iu = min(abs(uu), 64);
    int ib = min(abs(bq), 64);
    float sgu = (uv > 0.f) ? 1.f : ((uv < 0.f) ? -1.f : 0.f);
    float sgb = (bv > 0.f) ? 1.f : ((bv < 0.f) ? -1.f : 0.f);
    float x8 = (float)(iu * ib) * sgu * sgb;

    float ssv = (float)uu * SN2 * SN3;
    g_mean[j] = mean;
    g_c1[j]   = SN3 / ssv;          // x7 coefficient
    g_c2[j]   = x8 * SN2 / ssv;     // additive term

    int wc = max(-64, min(64, ww)); // signed-clamp == sign*clip(|.|,64)
    g_wc[j] = (float)wc;
}

// ---------------------------------------------------------------------------
// Pass 3 (persistent, grid-stride in reversed unit order): 888 blocks x 256
// threads. Iteration i of block b handles unit NCH-1-(b+i*NBP): the first
// chip-wide sweep touches the rows pass1 read most recently (L2-resident
// tail of X). Output stores __stcs so the written stream doesn't evict X.
// w-group g = row>>7 (repeat_interleave pairing: k//B == row>>7 exactly;
// 16-row units never straddle a 128-row group).
// out = clamp((int)((x-mean)*SN1), +-64) * (wc[g]*c1[j]) + c2[j]
// ---------------------------------------------------------------------------
__global__ void __launch_bounds__(256) k_pass3(const float* __restrict__ X,
                                               float* __restrict__ O) {
    const int tc = threadIdx.x & 127;   // column group 0..127
    const int tr = threadIdx.x >> 7;    // row parity 0..1

    float4 m  = reinterpret_cast<const float4*>(g_mean)[tc];
    float4 c1 = reinterpret_cast<const float4*>(g_c1)[tc];
    float4 c2 = reinterpret_cast<const float4*>(g_c2)[tc];
    const float sn1 = g_sn1;

    const float4* Xp = reinterpret_cast<const float4*>(X);
    float4* Op = reinterpret_cast<float4*>(O);
    const size_t rs = CDIM / 4;

    for (int i = blockIdx.x; i < NCH; i += NBP) {
        const int unit = NCH - 1 - i;         // reversed order
        const int row0 = unit * CHUNK;
        const float wg = g_wc[row0 >> 7];
        float4 e1;
        e1.x = wg * c1.x; e1.y = wg * c1.y;
        e1.z = wg * c1.z; e1.w = wg * c1.w;

        size_t base = (size_t)(row0 + tr) * rs + tc;
#pragma unroll
        for (int r = 0; r < CHUNK; r += 2) {
            float4 v = Xp[base + (size_t)r * rs];
            float4 o;
            {
                int q = (int)((v.x - m.x) * sn1);
                q = max(-64, min(64, q));
                o.x = (float)q * e1.x + c2.x;
            }
            {
                int q = (int)((v.y - m.y) * sn1);
                q = max(-64, min(64, q));
                o.y = (float)q * e1.y + c2.y;
            }
            {
                int q = (int)((v.z - m.z) * sn1);
                q = max(-64, min(64, q));
                o.z = (float)q * e1.z + c2.z;
            }
            {
                int q = (int)((v.w - m.w) * sn1);
                q = max(-64, min(64, q));
                o.w = (float)q * e1.w + c2.w;
            }
            __stcs(Op + base + (size_t)r * rs, o);
        }
    }
}

// ---------------------------------------------------------------------------
extern "C" void kernel_launch(void* const* d_in, const int* in_sizes, int n_in,
                              void* d_out, int out_size) {
    const float* X  = (const float*)d_in[0];   // (65536, 512)
    const float* w  = (const float*)d_in[1];   // (512,)
    const float* bi = (const float*)d_in[2];   // (512,)
    float* O = (float*)d_out;

    k_pass1<<<NBP, 256>>>(X);
    k_stage2a<<<NB2, CDIM>>>();
    k_stage2b<<<1, CDIM>>>(w, bi);
    k_pass3<<<NBP, 256>>>(X, O);
}